// round 14
// baseline (speedup 1.0000x reference)
#include <cuda_runtime.h>
#include <cuda_fp16.h>
#include <cstdint>

#define LSEQ 8192
#define DIM  2048
#define NCHUNK 128            // finer chunks: better block-level balance
#define CHUNK 64

// ---------------- scratch (__device__ globals; no allocation) ---------------
__device__ __half g_xmh[(size_t)LSEQ * DIM];   // x_mix, fp16
__device__ __half g_wh[(size_t)DIM * DIM];     // W, fp16
__device__ float g_carry[NCHUNK * DIM];
__device__ float g_mprev[NCHUNK * DIM];

__device__ __forceinline__ float sigmoidf_(float p) { return 1.0f / (1.0f + expf(-p)); }

// ---------------------------------------------------------------------------
// Pass A: per-chunk carry only. 2 dims per thread (float2), 128-thread CTAs.
// grid (DIM/256, NCHUNK) = (8, 128) = 1024 CTAs.
// ---------------------------------------------------------------------------
__global__ void carryscan_kernel(const float* __restrict__ x,
                                 const float* __restrict__ fparam) {
    int d2 = blockIdx.x * blockDim.x + threadIdx.x;   // float2 index
    int c = blockIdx.y;
    float2 fp = ((const float2*)fparam)[d2];
    float f0 = sigmoidf_(fp.x), f1 = sigmoidf_(fp.y);
    float o0 = 1.0f - f0, o1 = 1.0f - f1;
    const float2* xp = (const float2*)(x + (size_t)c * CHUNK * DIM) + d2;
    float y0 = 0.0f, y1 = 0.0f;
#pragma unroll 16
    for (int i = 0; i < CHUNK; i++) {
        float2 v = xp[(size_t)i * (DIM / 2)];
        y0 = fmaf(f0, y0, o0 * v.x);
        y1 = fmaf(f1, y1, o1 * v.y);
    }
    ((float2*)g_carry)[c * (DIM / 2) + d2] = make_float2(y0, y1);
}

// ---------------------------------------------------------------------------
// Pass B (fused): serial carry combine (blockIdx.y==0) + W -> fp16 conversion.
// 128-thread CTAs. carry: 8 blocks cover DIM/2 float2 dims.
// W: (WBY * 8) blocks * 128 threads * 4 float4 = DIM*DIM floats.
// ---------------------------------------------------------------------------
#define WBY 256
__global__ void carryw_kernel(const float* __restrict__ fparam,
                              const float* __restrict__ xml,
                              const float* __restrict__ W) {
    if (blockIdx.y == 0) {
        int d2 = blockIdx.x * blockDim.x + threadIdx.x;
        float2 fp = ((const float2*)fparam)[d2];
        float f0 = sigmoidf_(fp.x), f1 = sigmoidf_(fp.y);
        float c0 = f0, c1 = f1;
#pragma unroll
        for (int i = 0; i < 6; i++) { c0 *= c0; c1 *= c1; }   // f^64 = f^CHUNK
        float2 m = ((const float2*)xml)[d2];
#pragma unroll 4
        for (int c = 0; c < NCHUNK; c++) {
            ((float2*)g_mprev)[c * (DIM / 2) + d2] = m;
            float2 cy = ((const float2*)g_carry)[c * (DIM / 2) + d2];
            m.x = fmaf(c0, m.x, cy.x);
            m.y = fmaf(c1, m.y, cy.y);
        }
    } else {
        int q = ((blockIdx.y - 1) * gridDim.x + blockIdx.x) * blockDim.x + threadIdx.x;
        const int QE = (DIM * DIM / 4) / 4;   // 262144 float4s per quarter
#pragma unroll
        for (int r = 0; r < 4; r++) {
            float4 v = ((const float4*)W)[q + r * QE];
            ((__half2*)g_wh)[(q + r * QE) * 2]     = __floats2half2_rn(v.x, v.y);
            ((__half2*)g_wh)[(q + r * QE) * 2 + 1] = __floats2half2_rn(v.z, v.w);
        }
    }
}

// ---------------------------------------------------------------------------
// Pass C: seeded rescan -> fp16 x_mix. 2 dims/thread, 128-thread CTAs.
// ---------------------------------------------------------------------------
__global__ void scan_write_kernel(const float* __restrict__ x,
                                  const float* __restrict__ fparam) {
    int d2 = blockIdx.x * blockDim.x + threadIdx.x;
    int c = blockIdx.y;
    float2 fp = ((const float2*)fparam)[d2];
    float f0 = sigmoidf_(fp.x), f1 = sigmoidf_(fp.y);
    float o0 = 1.0f - f0, o1 = 1.0f - f1;
    const float2* xp = (const float2*)(x + (size_t)c * CHUNK * DIM) + d2;
    __half2* yp = (__half2*)(g_xmh + (size_t)c * CHUNK * DIM) + d2;
    float2 m = ((const float2*)g_mprev)[c * (DIM / 2) + d2];
    float y0 = m.x, y1 = m.y;
#pragma unroll 16
    for (int i = 0; i < CHUNK; i++) {
        float2 v = xp[(size_t)i * (DIM / 2)];
        y0 = fmaf(f0, y0, o0 * v.x);
        y1 = fmaf(f1, y1, o1 * v.y);
        yp[(size_t)i * (DIM / 2)] = __floats2half2_rn(y0, y1);
    }
}

// ---------------------------------------------------------------------------
// fp16 mma.sync GEMM:  out[m,n] = sum_k A[m,k] * W[n,k]  (fp32 accum)
// Block tile 128x128x64, 128 threads = 4 warps (2m x 2n), warp tile 64x64.
// 2 CTAs/SM, 3-stage cp.async ring. Tile-boundary wait+barrier+prime is
// software-pipelined into the ks=3 MMA shadow of the previous tile.
// (unchanged from R13: measured 144.3us, tensor=78.4%)
// ---------------------------------------------------------------------------
#define BM 128
#define BN 128
#define BK 64                                  // halfs; 128 bytes per row
#define KTILES (DIM / BK)                      // 32
#define A_BYTES (BM * 128)                     // 16384
#define B_BYTES (BN * 128)                     // 16384
#define STAGE_BYTES (A_BYTES + B_BYTES)        // 32768
#define NSTAGE 3
#define SM_BYTES (NSTAGE * STAGE_BYTES)        // 98304

#define MMA_F16(c, a, b0, b1)                                                 \
    asm volatile(                                                             \
        "mma.sync.aligned.m16n8k16.row.col.f32.f16.f16.f32 "                  \
        "{%0,%1,%2,%3},{%4,%5,%6,%7},{%8,%9},{%0,%1,%2,%3};\n"                \
        : "+f"((c)[0]), "+f"((c)[1]), "+f"((c)[2]), "+f"((c)[3])              \
        : "r"((a)[0]), "r"((a)[1]), "r"((a)[2]), "r"((a)[3]),                 \
          "r"(b0), "r"(b1))

__device__ __forceinline__ uint32_t smem_u32(const void* p) {
    uint32_t a;
    asm("{ .reg .u64 t; cvta.to.shared.u64 t, %1; cvt.u32.u64 %0, t; }" : "=r"(a) : "l"(p));
    return a;
}
__device__ __forceinline__ void cp16(uint32_t dst, const void* src) {
    asm volatile("cp.async.cg.shared.global [%0], [%1], 16;" :: "r"(dst), "l"(src));
}
__device__ __forceinline__ void cp_commit() {
    asm volatile("cp.async.commit_group;");
}
template <int N>
__device__ __forceinline__ void cp_wait() {
    asm volatile("cp.async.wait_group %0;" :: "n"(N));
}
__device__ __forceinline__ void ldsm4(unsigned* r, uint32_t addr) {
    asm volatile("ldmatrix.sync.aligned.m8n8.x4.shared.b16 {%0,%1,%2,%3}, [%4];"
                 : "=r"(r[0]), "=r"(r[1]), "=r"(r[2]), "=r"(r[3]) : "r"(addr));
}

__global__ __launch_bounds__(128, 2) void gemm_kernel(float* __restrict__ out) {
    extern __shared__ char smc[];
    uint32_t sb = smem_u32(smc);

    int tid = threadIdx.x;
    int bm = blockIdx.y * BM, bn = blockIdx.x * BN;
    int warp = tid >> 5, lane = tid & 31;
    int wm = (warp & 1) * 64, wn = (warp >> 1) * 64;
    int grp = lane >> 2, tig = lane & 3;

    // cp.async thread mapping: 16B chunks, swizzle chunk ^= row&7
    int lrow = tid >> 3;            // 0..15
    int lch = tid & 7;              // chunk 0..7
    uint32_t stoffA = lrow * 128 + ((lch ^ (lrow & 7)) << 4);
    uint32_t stoffB = A_BYTES + stoffA;

    const __half* Ag = g_xmh + (size_t)(bm + lrow) * DIM + lch * 8;
    const __half* Bg = g_wh + (size_t)(bn + lrow) * DIM + lch * 8;

    // ldmatrix per-lane address components
    uint32_t aBase[4]; int aR7[4];
    int aCC = lane >> 4;            // kc parity offset
    {
        int r = (lane & 7) + ((lane >> 3) & 1) * 8;
#pragma unroll
        for (int mt = 0; mt < 4; mt++) {
            int row = wm + mt * 16 + r;
            aBase[mt] = row * 128;
            aR7[mt] = row & 7;
        }
    }
    uint32_t bBase[4]; int bR7[4];
    int bCC = (lane >> 3) & 1;
    {
        int r = (lane & 7) + ((lane >> 4) & 1) * 8;
#pragma unroll
        for (int p = 0; p < 4; p++) {
            int row = wn + p * 16 + r;
            bBase[p] = A_BYTES + row * 128;
            bR7[p] = row & 7;
        }
    }

    float acc[4][8][4] = {};

    auto issue = [&](int t) {
        int slot = t % NSTAGE;
        uint32_t base = sb + slot * STAGE_BYTES;
        const __half* Ak = Ag + t * BK;
        const __half* Bk = Bg + t * BK;
#pragma unroll
        for (int o = 0; o < 8; o++)
            cp16(base + stoffA + o * (16 * 128), Ak + (size_t)(o * 16) * DIM);
#pragma unroll
        for (int o = 0; o < 8; o++)
            cp16(base + stoffB + o * (16 * 128), Bk + (size_t)(o * 16) * DIM);
        cp_commit();
    };

    unsigned a[2][4][4], b[2][4][4];

    // prime fragments (k-chunk kc) from stage base st into buffer q
    auto prime = [&](int q, uint32_t st, int kc) {
#pragma unroll
        for (int mt = 0; mt < 4; mt++)
            ldsm4(a[q][mt], st + aBase[mt] + (((kc + aCC) ^ aR7[mt]) << 4));
#pragma unroll
        for (int p = 0; p < 4; p++)
            ldsm4(b[q][p], st + bBase[p] + (((kc + bCC) ^ bR7[p]) << 4));
    };

    // ---- prologue ----
    issue(0);
    issue(1);
    cp_wait<1>();
    __syncthreads();
    prime(0, sb, 0);          // tile 0, ks=0 -> buffer 0

    int slot = 0;
    for (int j = 0; j < KTILES; j++) {
        uint32_t st = sb + slot * STAGE_BYTES;
        // refill slot (j+2)%3: all warps passed the barrier before reading
        // tile j, i.e. after their last read of tile j-1 (same slot). Safe.
        if (j + 2 < KTILES) issue(j + 2);

#pragma unroll
        for (int ks = 0; ks < 4; ks++) {
            int cur = ks & 1, nxt = cur ^ 1;
            if (ks < 3) {
                prime(nxt, st, 2 * (ks + 1));
            } else if (j + 1 < KTILES) {
                // tile boundary inside the ks=3 MMA shadow
                if (j + 2 < KTILES) { cp_wait<1>(); }   // {j+1,j+2} -> j+1 done
                else { cp_wait<0>(); }                  // only {j+1} in flight
                __syncthreads();
                int slot2 = slot + 1 == NSTAGE ? 0 : slot + 1;
                prime(nxt, sb + slot2 * STAGE_BYTES, 0);
            }
#pragma unroll
            for (int mt = 0; mt < 4; mt++)
#pragma unroll
                for (int p = 0; p < 4; p++) {
                    MMA_F16(acc[mt][2 * p], a[cur][mt], b[cur][p][0], b[cur][p][1]);
                    MMA_F16(acc[mt][2 * p + 1], a[cur][mt], b[cur][p][2], b[cur][p][3]);
                }
        }

        slot++; if (slot == NSTAGE) slot = 0;
    }

    // ---- epilogue: float2 stores ----
#pragma unroll
    for (int mt = 0; mt < 4; mt++) {
#pragma unroll
        for (int nt = 0; nt < 8; nt++) {
            int row = bm + wm + mt * 16 + grp;
            int col = bn + wn + nt * 8 + tig * 2;
            float2 v0 = make_float2(acc[mt][nt][0], acc[mt][nt][1]);
            float2 v1 = make_float2(acc[mt][nt][2], acc[mt][nt][3]);
            *(float2*)(out + (size_t)row * DIM + col) = v0;
            *(float2*)(out + (size_t)(row + 8) * DIM + col) = v1;
        }
    }
}

// ---------------------------------------------------------------------------
extern "C" void kernel_launch(void* const* d_in, const int* in_sizes, int n_in,
                              void* d_out, int out_size) {
    const float* x      = (const float*)d_in[0];
    const float* xml    = (const float*)d_in[1];
    const float* fparam = (const float*)d_in[2];
    const float* W      = (const float*)d_in[3];
    float* out = (float*)d_out;

    // passes A/C: 1024 CTAs of 128 threads (2 dims/thread, fine chunks)
    carryscan_kernel<<<dim3(DIM / 256, NCHUNK), 128>>>(x, fparam);
    carryw_kernel<<<dim3(DIM / 256, 1 + WBY), 128>>>(fparam, xml, W);
    scan_write_kernel<<<dim3(DIM / 256, NCHUNK), 128>>>(x, fparam);

    static bool attr_set = false;
    if (!attr_set) {
        cudaFuncSetAttribute(gemm_kernel, cudaFuncAttributeMaxDynamicSharedMemorySize, SM_BYTES);
        attr_set = true;
    }
    gemm_kernel<<<dim3(DIM / BN, LSEQ / BM), 128, SM_BYTES>>>(out);
}

// round 15
// speedup vs baseline: 1.0612x; 1.0612x over previous
#include <cuda_runtime.h>
#include <cuda_fp16.h>
#include <cstdint>

#define LSEQ 8192
#define DIM  2048
#define NCHUNK 64
#define CHUNK 128

// ---------------- scratch (__device__ globals; no allocation) ---------------
__device__ __half g_xmh[(size_t)LSEQ * DIM];   // x_mix, fp16
__device__ __half g_wh[(size_t)DIM * DIM];     // W, fp16
__device__ float g_carry[NCHUNK * DIM];
__device__ float g_mprev[NCHUNK * DIM];

__device__ __forceinline__ float sigmoidf_(float p) { return 1.0f / (1.0f + expf(-p)); }

// ---------------------------------------------------------------------------
// Pass A: per-chunk carry only (zero-seeded local scan). Scalar layout:
// one warp-LDG = one 128B sector, max warps in flight. (R12-measured config)
// ---------------------------------------------------------------------------
__global__ void carryscan_kernel(const float* __restrict__ x,
                                 const float* __restrict__ fparam) {
    int d = blockIdx.x * blockDim.x + threadIdx.x;
    int c = blockIdx.y;
    float f = sigmoidf_(fparam[d]);
    float omf = 1.0f - f;
    const float* xp = x + (size_t)c * CHUNK * DIM + d;
    float y = 0.0f;
#pragma unroll 16
    for (int i = 0; i < CHUNK; i++)
        y = fmaf(f, y, omf * xp[(size_t)i * DIM]);
    g_carry[c * DIM + d] = y;
}

// ---------------------------------------------------------------------------
// Pass B (fused): serial carry combine (blockIdx.y == 0, 8 blocks)
// + W -> fp16 conversion (blockIdx.y >= 1, 2 float4 per thread).
// ---------------------------------------------------------------------------
#define WBY 256
__global__ void carryw_kernel(const float* __restrict__ fparam,
                              const float* __restrict__ xml,
                              const float* __restrict__ W) {
    if (blockIdx.y == 0) {
        int d = blockIdx.x * blockDim.x + threadIdx.x;
        float f = sigmoidf_(fparam[d]);
        float fC = f;
#pragma unroll
        for (int i = 0; i < 7; i++) fC *= fC;   // f^128
        float m = xml[d];
#pragma unroll 4
        for (int c = 0; c < NCHUNK; c++) {
            g_mprev[c * DIM + d] = m;
            m = fmaf(fC, m, g_carry[c * DIM + d]);
        }
    } else {
        // (WBY * gridDim.x) blocks * 256 threads * 2 float4 = DIM*DIM floats
        int q = ((blockIdx.y - 1) * gridDim.x + blockIdx.x) * blockDim.x + threadIdx.x;
        const int HALF_ELEMS = (DIM * DIM / 4) / 2;   // 524288
        float4 v0 = ((const float4*)W)[q];
        float4 v1 = ((const float4*)W)[q + HALF_ELEMS];
        ((__half2*)g_wh)[q * 2]     = __floats2half2_rn(v0.x, v0.y);
        ((__half2*)g_wh)[q * 2 + 1] = __floats2half2_rn(v0.z, v0.w);
        ((__half2*)g_wh)[(q + HALF_ELEMS) * 2]     = __floats2half2_rn(v1.x, v1.y);
        ((__half2*)g_wh)[(q + HALF_ELEMS) * 2 + 1] = __floats2half2_rn(v1.z, v1.w);
    }
}

// ---------------------------------------------------------------------------
// Pass C: seeded rescan, writes fp16 x_mix. Scalar layout (R12-measured).
// ---------------------------------------------------------------------------
__global__ void scan_write_kernel(const float* __restrict__ x,
                                  const float* __restrict__ fparam) {
    int d = blockIdx.x * blockDim.x + threadIdx.x;
    int c = blockIdx.y;
    float f = sigmoidf_(fparam[d]);
    float omf = 1.0f - f;
    const float* xp = x + (size_t)c * CHUNK * DIM + d;
    __half* yp = g_xmh + (size_t)c * CHUNK * DIM + d;
    float y = g_mprev[c * DIM + d];
#pragma unroll 16
    for (int i = 0; i < CHUNK; i++) {
        y = fmaf(f, y, omf * xp[(size_t)i * DIM]);
        yp[(size_t)i * DIM] = __float2half_rn(y);
    }
}

// ---------------------------------------------------------------------------
// fp16 mma.sync GEMM:  out[m,n] = sum_k A[m,k] * W[n,k]  (fp32 accum)
// Block tile 128x128x64, 128 threads = 4 warps (2m x 2n), warp tile 64x64.
// 2 CTAs/SM, 3-stage cp.async ring. Tile-boundary wait+barrier+prime is
// software-pipelined into the ks=3 MMA shadow of the previous tile.
// (R13-measured: 144.3us, tensor=78.4%)
// ---------------------------------------------------------------------------
#define BM 128
#define BN 128
#define BK 64                                  // halfs; 128 bytes per row
#define KTILES (DIM / BK)                      // 32
#define A_BYTES (BM * 128)                     // 16384
#define B_BYTES (BN * 128)                     // 16384
#define STAGE_BYTES (A_BYTES + B_BYTES)        // 32768
#define NSTAGE 3
#define SM_BYTES (NSTAGE * STAGE_BYTES)        // 98304

#define MMA_F16(c, a, b0, b1)                                                 \
    asm volatile(                                                             \
        "mma.sync.aligned.m16n8k16.row.col.f32.f16.f16.f32 "                  \
        "{%0,%1,%2,%3},{%4,%5,%6,%7},{%8,%9},{%0,%1,%2,%3};\n"                \
        : "+f"((c)[0]), "+f"((c)[1]), "+f"((c)[2]), "+f"((c)[3])              \
        : "r"((a)[0]), "r"((a)[1]), "r"((a)[2]), "r"((a)[3]),                 \
          "r"(b0), "r"(b1))

__device__ __forceinline__ uint32_t smem_u32(const void* p) {
    uint32_t a;
    asm("{ .reg .u64 t; cvta.to.shared.u64 t, %1; cvt.u32.u64 %0, t; }" : "=r"(a) : "l"(p));
    return a;
}
__device__ __forceinline__ void cp16(uint32_t dst, const void* src) {
    asm volatile("cp.async.cg.shared.global [%0], [%1], 16;" :: "r"(dst), "l"(src));
}
__device__ __forceinline__ void cp_commit() {
    asm volatile("cp.async.commit_group;");
}
template <int N>
__device__ __forceinline__ void cp_wait() {
    asm volatile("cp.async.wait_group %0;" :: "n"(N));
}
__device__ __forceinline__ void ldsm4(unsigned* r, uint32_t addr) {
    asm volatile("ldmatrix.sync.aligned.m8n8.x4.shared.b16 {%0,%1,%2,%3}, [%4];"
                 : "=r"(r[0]), "=r"(r[1]), "=r"(r[2]), "=r"(r[3]) : "r"(addr));
}

__global__ __launch_bounds__(128, 2) void gemm_kernel(float* __restrict__ out) {
    extern __shared__ char smc[];
    uint32_t sb = smem_u32(smc);

    int tid = threadIdx.x;
    int bm = blockIdx.y * BM, bn = blockIdx.x * BN;
    int warp = tid >> 5, lane = tid & 31;
    int wm = (warp & 1) * 64, wn = (warp >> 1) * 64;
    int grp = lane >> 2, tig = lane & 3;

    // cp.async thread mapping: 16B chunks, swizzle chunk ^= row&7
    int lrow = tid >> 3;            // 0..15
    int lch = tid & 7;              // chunk 0..7
    uint32_t stoffA = lrow * 128 + ((lch ^ (lrow & 7)) << 4);
    uint32_t stoffB = A_BYTES + stoffA;

    const __half* Ag = g_xmh + (size_t)(bm + lrow) * DIM + lch * 8;
    const __half* Bg = g_wh + (size_t)(bn + lrow) * DIM + lch * 8;

    // ldmatrix per-lane address components
    uint32_t aBase[4]; int aR7[4];
    int aCC = lane >> 4;            // kc parity offset
    {
        int r = (lane & 7) + ((lane >> 3) & 1) * 8;
#pragma unroll
        for (int mt = 0; mt < 4; mt++) {
            int row = wm + mt * 16 + r;
            aBase[mt] = row * 128;
            aR7[mt] = row & 7;
        }
    }
    uint32_t bBase[4]; int bR7[4];
    int bCC = (lane >> 3) & 1;
    {
        int r = (lane & 7) + ((lane >> 4) & 1) * 8;
#pragma unroll
        for (int p = 0; p < 4; p++) {
            int row = wn + p * 16 + r;
            bBase[p] = A_BYTES + row * 128;
            bR7[p] = row & 7;
        }
    }

    float acc[4][8][4] = {};

    auto issue = [&](int t) {
        int slot = t % NSTAGE;
        uint32_t base = sb + slot * STAGE_BYTES;
        const __half* Ak = Ag + t * BK;
        const __half* Bk = Bg + t * BK;
#pragma unroll
        for (int o = 0; o < 8; o++)
            cp16(base + stoffA + o * (16 * 128), Ak + (size_t)(o * 16) * DIM);
#pragma unroll
        for (int o = 0; o < 8; o++)
            cp16(base + stoffB + o * (16 * 128), Bk + (size_t)(o * 16) * DIM);
        cp_commit();
    };

    unsigned a[2][4][4], b[2][4][4];

    // prime fragments (k-chunk kc) from stage base st into buffer q
    auto prime = [&](int q, uint32_t st, int kc) {
#pragma unroll
        for (int mt = 0; mt < 4; mt++)
            ldsm4(a[q][mt], st + aBase[mt] + (((kc + aCC) ^ aR7[mt]) << 4));
#pragma unroll
        for (int p = 0; p < 4; p++)
            ldsm4(b[q][p], st + bBase[p] + (((kc + bCC) ^ bR7[p]) << 4));
    };

    // ---- prologue ----
    issue(0);
    issue(1);
    cp_wait<1>();
    __syncthreads();
    prime(0, sb, 0);          // tile 0, ks=0 -> buffer 0

    int slot = 0;
    for (int j = 0; j < KTILES; j++) {
        uint32_t st = sb + slot * STAGE_BYTES;
        // refill slot (j+2)%3: all warps passed the barrier before reading
        // tile j, i.e. after their last read of tile j-1 (same slot). Safe.
        if (j + 2 < KTILES) issue(j + 2);

#pragma unroll
        for (int ks = 0; ks < 4; ks++) {
            int cur = ks & 1, nxt = cur ^ 1;
            if (ks < 3) {
                prime(nxt, st, 2 * (ks + 1));
            } else if (j + 1 < KTILES) {
                // tile boundary inside the ks=3 MMA shadow
                if (j + 2 < KTILES) { cp_wait<1>(); }   // {j+1,j+2} -> j+1 done
                else { cp_wait<0>(); }                  // only {j+1} in flight
                __syncthreads();
                int slot2 = slot + 1 == NSTAGE ? 0 : slot + 1;
                prime(nxt, sb + slot2 * STAGE_BYTES, 0);
            }
#pragma unroll
            for (int mt = 0; mt < 4; mt++)
#pragma unroll
                for (int p = 0; p < 4; p++) {
                    MMA_F16(acc[mt][2 * p], a[cur][mt], b[cur][p][0], b[cur][p][1]);
                    MMA_F16(acc[mt][2 * p + 1], a[cur][mt], b[cur][p][2], b[cur][p][3]);
                }
        }

        slot++; if (slot == NSTAGE) slot = 0;
    }

    // ---- epilogue: float2 stores ----
#pragma unroll
    for (int mt = 0; mt < 4; mt++) {
#pragma unroll
        for (int nt = 0; nt < 8; nt++) {
            int row = bm + wm + mt * 16 + grp;
            int col = bn + wn + nt * 8 + tig * 2;
            float2 v0 = make_float2(acc[mt][nt][0], acc[mt][nt][1]);
            float2 v1 = make_float2(acc[mt][nt][2], acc[mt][nt][3]);
            *(float2*)(out + (size_t)row * DIM + col) = v0;
            *(float2*)(out + (size_t)(row + 8) * DIM + col) = v1;
        }
    }
}

// ---------------------------------------------------------------------------
extern "C" void kernel_launch(void* const* d_in, const int* in_sizes, int n_in,
                              void* d_out, int out_size) {
    const float* x      = (const float*)d_in[0];
    const float* xml    = (const float*)d_in[1];
    const float* fparam = (const float*)d_in[2];
    const float* W      = (const float*)d_in[3];
    float* out = (float*)d_out;

    // scan chain: exact R12 configuration (measured 49.6us)
    carryscan_kernel<<<dim3(DIM / 256, NCHUNK), 256>>>(x, fparam);
    carryw_kernel<<<dim3(DIM / 256, 1 + WBY), 256>>>(fparam, xml, W);
    scan_write_kernel<<<dim3(DIM / 256, NCHUNK), 256>>>(x, fparam);

    static bool attr_set = false;
    if (!attr_set) {
        cudaFuncSetAttribute(gemm_kernel, cudaFuncAttributeMaxDynamicSharedMemorySize, SM_BYTES);
        attr_set = true;
    }
    gemm_kernel<<<dim3(DIM / BN, LSEQ / BM), 128, SM_BYTES>>>(out);
}

// round 16
// speedup vs baseline: 1.0689x; 1.0073x over previous
#include <cuda_runtime.h>
#include <cuda_fp16.h>
#include <cstdint>

#define LSEQ 8192
#define DIM  2048
#define NCHUNK 64
#define CHUNK 128
#define XBLKS (DIM / 256)       // 8 x-blocks of 256 dims

// ---------------- scratch (__device__ globals; no allocation) ---------------
__device__ __half g_xmh[(size_t)LSEQ * DIM];   // x_mix, fp16
__device__ __half g_wh[(size_t)DIM * DIM];     // W, fp16
__device__ float g_carry[NCHUNK * DIM];        // per-chunk local aggregates Y[c]
__device__ float g_prefix[NCHUNK * DIM];       // inclusive prefixes M[c]
__device__ int   g_flag[NCHUNK * XBLKS];       // 0=empty, 1=aggregate, 2=prefix

__device__ __forceinline__ float sigmoidf_(float p) { return 1.0f / (1.0f + expf(-p)); }

__device__ __forceinline__ int ld_acq(const int* p) {
    int v;
    asm volatile("ld.acquire.gpu.global.b32 %0, [%1];" : "=r"(v) : "l"(p) : "memory");
    return v;
}
__device__ __forceinline__ void st_rel(int* p, int v) {
    asm volatile("st.release.gpu.global.b32 [%0], %1;" :: "l"(p), "r"(v) : "memory");
}

// ---------------------------------------------------------------------------
// Flag reset (per launch; graph-replay safe, no persistent state)
// ---------------------------------------------------------------------------
__global__ void reset_kernel() { g_flag[threadIdx.x] = 0; }

// ---------------------------------------------------------------------------
// Fused decoupled-lookback scan + W->fp16 conversion.
// blockIdx.y <  NCHUNK : scan CTA for (xblock=blockIdx.x, chunk=blockIdx.y)
// blockIdx.y >= NCHUNK : W conversion rows (no lookback participation)
// All 512 scan CTAs are co-resident (one wave) -> lookback is short.
// ---------------------------------------------------------------------------
#define WROWS 128
__global__ void scan_fused_kernel(const float* __restrict__ x,
                                  const float* __restrict__ fparam,
                                  const float* __restrict__ xml,
                                  const float* __restrict__ W) {
    if (blockIdx.y >= NCHUNK) {
        // ---- W conversion: 1024 blocks * 256 thr * 4 float4 = DIM*DIM ----
        int idx = (blockIdx.y - NCHUNK) * gridDim.x + blockIdx.x;
        int q = idx * blockDim.x + threadIdx.x;
        const int QE = (DIM * DIM / 4) / 4;   // 262144
#pragma unroll
        for (int r = 0; r < 4; r++) {
            float4 v = ((const float4*)W)[q + r * QE];
            ((__half2*)g_wh)[(q + r * QE) * 2]     = __floats2half2_rn(v.x, v.y);
            ((__half2*)g_wh)[(q + r * QE) * 2 + 1] = __floats2half2_rn(v.z, v.w);
        }
        return;
    }

    int xb = blockIdx.x, c = blockIdx.y, tid = threadIdx.x;
    int d = xb * 256 + tid;
    float f = sigmoidf_(fparam[d]);
    float omf = 1.0f - f;
    float fC = f;
#pragma unroll
    for (int i = 0; i < 7; i++) fC *= fC;     // f^128 = f^CHUNK

    const float* xp = x + (size_t)c * CHUNK * DIM + d;

    // ---- phase 1: chunk-local scan (zero seed) ----
    float y = 0.0f;
#pragma unroll 16
    for (int i = 0; i < CHUNK; i++)
        y = fmaf(f, y, omf * xp[(size_t)i * DIM]);

    // ---- publish aggregate Y[c] ----
    g_carry[c * DIM + d] = y;
    __threadfence();
    __syncthreads();
    if (tid == 0) st_rel(&g_flag[c * XBLKS + xb], 1);

    // ---- lookback: mprev = M[c-1] ----
    float mprev;
    if (c == 0) {
        mprev = xml[d];
    } else {
        __shared__ int s_stop;
        if (tid < 32) {
            // warp-parallel poll: lane k covers cc = c-1-k and c-33-k
            int cc1 = c - 1 - tid;
            int cc2 = cc1 - 32;
            while (true) {
                int fl1 = (cc1 >= 0) ? ld_acq(&g_flag[cc1 * XBLKS + xb]) : 3;
                int fl2 = (cc2 >= 0) ? ld_acq(&g_flag[cc2 * XBLKS + xb]) : 3;
                bool ready = __all_sync(0xFFFFFFFFu, (fl1 != 0) && (fl2 != 0));
                if (ready) {
                    unsigned m1 = __ballot_sync(0xFFFFFFFFu, fl1 == 2);
                    unsigned m2 = __ballot_sync(0xFFFFFFFFu, fl2 == 2);
                    int stop;
                    if (m1)      stop = c - 1 - (__ffs(m1) - 1);
                    else if (m2) stop = c - 33 - (__ffs(m2) - 1);
                    else         stop = -1;
                    if (tid == 0) s_stop = stop;
                    break;
                }
                __nanosleep(64);
            }
        }
        __syncthreads();
        int stop = s_stop;
        // acc = sum_{cc=stop+1..c-1} fC^(c-1-cc) * Y[cc]  (+ prefix/xml tail)
        float acc = 0.0f, factor = 1.0f;
        for (int cc = c - 1; cc > stop; cc--) {
            acc = fmaf(factor, g_carry[cc * DIM + d], acc);
            factor *= fC;
        }
        if (stop >= 0) acc = fmaf(factor, g_prefix[stop * DIM + d], acc);
        else           acc = fmaf(factor, xml[d], acc);
        mprev = acc;
    }

    // ---- publish inclusive prefix M[c] = fC*M[c-1] + Y[c] ----
    g_prefix[c * DIM + d] = fmaf(fC, mprev, y);
    __threadfence();
    __syncthreads();
    if (tid == 0) st_rel(&g_flag[c * XBLKS + xb], 2);

    // ---- phase 3: seeded rescan (x chunk is L2-warm), write fp16 ----
    __half* yp = g_xmh + (size_t)c * CHUNK * DIM + d;
    float yy = mprev;
#pragma unroll 16
    for (int i = 0; i < CHUNK; i++) {
        yy = fmaf(f, yy, omf * xp[(size_t)i * DIM]);
        yp[(size_t)i * DIM] = __float2half_rn(yy);
    }
}

// ---------------------------------------------------------------------------
// fp16 mma.sync GEMM:  out[m,n] = sum_k A[m,k] * W[n,k]  (fp32 accum)
// Block tile 128x128x64, 128 threads = 4 warps (2m x 2n), warp tile 64x64.
// 2 CTAs/SM, 3-stage cp.async ring, boundary prime in ks=3 MMA shadow.
// (R13/R15-measured: 144.3-144.7us, tensor=78.5% — unchanged)
// ---------------------------------------------------------------------------
#define BM 128
#define BN 128
#define BK 64
#define KTILES (DIM / BK)
#define A_BYTES (BM * 128)
#define B_BYTES (BN * 128)
#define STAGE_BYTES (A_BYTES + B_BYTES)
#define NSTAGE 3
#define SM_BYTES (NSTAGE * STAGE_BYTES)

#define MMA_F16(c, a, b0, b1)                                                 \
    asm volatile(                                                             \
        "mma.sync.aligned.m16n8k16.row.col.f32.f16.f16.f32 "                  \
        "{%0,%1,%2,%3},{%4,%5,%6,%7},{%8,%9},{%0,%1,%2,%3};\n"                \
        : "+f"((c)[0]), "+f"((c)[1]), "+f"((c)[2]), "+f"((c)[3])              \
        : "r"((a)[0]), "r"((a)[1]), "r"((a)[2]), "r"((a)[3]),                 \
          "r"(b0), "r"(b1))

__device__ __forceinline__ uint32_t smem_u32(const void* p) {
    uint32_t a;
    asm("{ .reg .u64 t; cvta.to.shared.u64 t, %1; cvt.u32.u64 %0, t; }" : "=r"(a) : "l"(p));
    return a;
}
__device__ __forceinline__ void cp16(uint32_t dst, const void* src) {
    asm volatile("cp.async.cg.shared.global [%0], [%1], 16;" :: "r"(dst), "l"(src));
}
__device__ __forceinline__ void cp_commit() {
    asm volatile("cp.async.commit_group;");
}
template <int N>
__device__ __forceinline__ void cp_wait() {
    asm volatile("cp.async.wait_group %0;" :: "n"(N));
}
__device__ __forceinline__ void ldsm4(unsigned* r, uint32_t addr) {
    asm volatile("ldmatrix.sync.aligned.m8n8.x4.shared.b16 {%0,%1,%2,%3}, [%4];"
                 : "=r"(r[0]), "=r"(r[1]), "=r"(r[2]), "=r"(r[3]) : "r"(addr));
}

__global__ __launch_bounds__(128, 2) void gemm_kernel(float* __restrict__ out) {
    extern __shared__ char smc[];
    uint32_t sb = smem_u32(smc);

    int tid = threadIdx.x;
    int bm = blockIdx.y * BM, bn = blockIdx.x * BN;
    int warp = tid >> 5, lane = tid & 31;
    int wm = (warp & 1) * 64, wn = (warp >> 1) * 64;
    int grp = lane >> 2, tig = lane & 3;

    int lrow = tid >> 3;
    int lch = tid & 7;
    uint32_t stoffA = lrow * 128 + ((lch ^ (lrow & 7)) << 4);
    uint32_t stoffB = A_BYTES + stoffA;

    const __half* Ag = g_xmh + (size_t)(bm + lrow) * DIM + lch * 8;
    const __half* Bg = g_wh + (size_t)(bn + lrow) * DIM + lch * 8;

    uint32_t aBase[4]; int aR7[4];
    int aCC = lane >> 4;
    {
        int r = (lane & 7) + ((lane >> 3) & 1) * 8;
#pragma unroll
        for (int mt = 0; mt < 4; mt++) {
            int row = wm + mt * 16 + r;
            aBase[mt] = row * 128;
            aR7[mt] = row & 7;
        }
    }
    uint32_t bBase[4]; int bR7[4];
    int bCC = (lane >> 3) & 1;
    {
        int r = (lane & 7) + ((lane >> 4) & 1) * 8;
#pragma unroll
        for (int p = 0; p < 4; p++) {
            int row = wn + p * 16 + r;
            bBase[p] = A_BYTES + row * 128;
            bR7[p] = row & 7;
        }
    }

    float acc[4][8][4] = {};

    auto issue = [&](int t) {
        int slot = t % NSTAGE;
        uint32_t base = sb + slot * STAGE_BYTES;
        const __half* Ak = Ag + t * BK;
        const __half* Bk = Bg + t * BK;
#pragma unroll
        for (int o = 0; o < 8; o++)
            cp16(base + stoffA + o * (16 * 128), Ak + (size_t)(o * 16) * DIM);
#pragma unroll
        for (int o = 0; o < 8; o++)
            cp16(base + stoffB + o * (16 * 128), Bk + (size_t)(o * 16) * DIM);
        cp_commit();
    };

    unsigned a[2][4][4], b[2][4][4];

    auto prime = [&](int q, uint32_t st, int kc) {
#pragma unroll
        for (int mt = 0; mt < 4; mt++)
            ldsm4(a[q][mt], st + aBase[mt] + (((kc + aCC) ^ aR7[mt]) << 4));
#pragma unroll
        for (int p = 0; p < 4; p++)
            ldsm4(b[q][p], st + bBase[p] + (((kc + bCC) ^ bR7[p]) << 4));
    };

    issue(0);
    issue(1);
    cp_wait<1>();
    __syncthreads();
    prime(0, sb, 0);

    int slot = 0;
    for (int j = 0; j < KTILES; j++) {
        uint32_t st = sb + slot * STAGE_BYTES;
        if (j + 2 < KTILES) issue(j + 2);

#pragma unroll
        for (int ks = 0; ks < 4; ks++) {
            int cur = ks & 1, nxt = cur ^ 1;
            if (ks < 3) {
                prime(nxt, st, 2 * (ks + 1));
            } else if (j + 1 < KTILES) {
                if (j + 2 < KTILES) { cp_wait<1>(); }
                else { cp_wait<0>(); }
                __syncthreads();
                int slot2 = slot + 1 == NSTAGE ? 0 : slot + 1;
                prime(nxt, sb + slot2 * STAGE_BYTES, 0);
            }
#pragma unroll
            for (int mt = 0; mt < 4; mt++)
#pragma unroll
                for (int p = 0; p < 4; p++) {
                    MMA_F16(acc[mt][2 * p], a[cur][mt], b[cur][p][0], b[cur][p][1]);
                    MMA_F16(acc[mt][2 * p + 1], a[cur][mt], b[cur][p][2], b[cur][p][3]);
                }
        }

        slot++; if (slot == NSTAGE) slot = 0;
    }

#pragma unroll
    for (int mt = 0; mt < 4; mt++) {
#pragma unroll
        for (int nt = 0; nt < 8; nt++) {
            int row = bm + wm + mt * 16 + grp;
            int col = bn + wn + nt * 8 + tig * 2;
            float2 v0 = make_float2(acc[mt][nt][0], acc[mt][nt][1]);
            float2 v1 = make_float2(acc[mt][nt][2], acc[mt][nt][3]);
            *(float2*)(out + (size_t)row * DIM + col) = v0;
            *(float2*)(out + (size_t)(row + 8) * DIM + col) = v1;
        }
    }
}

// ---------------------------------------------------------------------------
extern "C" void kernel_launch(void* const* d_in, const int* in_sizes, int n_in,
                              void* d_out, int out_size) {
    const float* x      = (const float*)d_in[0];
    const float* xml    = (const float*)d_in[1];
    const float* fparam = (const float*)d_in[2];
    const float* W      = (const float*)d_in[3];
    float* out = (float*)d_out;

    reset_kernel<<<1, NCHUNK * XBLKS>>>();
    scan_fused_kernel<<<dim3(XBLKS, NCHUNK + WROWS), 256>>>(x, fparam, xml, W);

    static bool attr_set = false;
    if (!attr_set) {
        cudaFuncSetAttribute(gemm_kernel, cudaFuncAttributeMaxDynamicSharedMemorySize, SM_BYTES);
        attr_set = true;
    }
    gemm_kernel<<<dim3(DIM / BN, LSEQ / BM), 128, SM_BYTES>>>(out);
}

// round 17
// speedup vs baseline: 1.0842x; 1.0143x over previous
#include <cuda_runtime.h>
#include <cuda_fp16.h>
#include <cstdint>

#define LSEQ 8192
#define DIM  2048
#define NCHUNK 64
#define CHUNK 128
#define XBLKS (DIM / 256)       // 8 x-blocks of 256 dims

// ---------------- scratch (__device__ globals; no allocation) ---------------
__device__ __half g_xmh[(size_t)LSEQ * DIM];   // x_mix, fp16
__device__ __half g_wh[(size_t)DIM * DIM];     // W, fp16
__device__ float g_carry[NCHUNK * DIM];        // per-chunk local aggregates Y[c]
__device__ float g_prefix[NCHUNK * DIM];       // inclusive prefixes M[c]
__device__ int   g_flag[NCHUNK * XBLKS];       // 0=empty, 1=aggregate, 2=prefix
                                               // (zero-init at load; re-zeroed
                                               //  by gemm_kernel each replay)

__device__ __forceinline__ float sigmoidf_(float p) { return 1.0f / (1.0f + expf(-p)); }

__device__ __forceinline__ int ld_acq(const int* p) {
    int v;
    asm volatile("ld.acquire.gpu.global.b32 %0, [%1];" : "=r"(v) : "l"(p) : "memory");
    return v;
}
__device__ __forceinline__ void st_rel(int* p, int v) {
    asm volatile("st.release.gpu.global.b32 [%0], %1;" :: "l"(p), "r"(v) : "memory");
}

// ---------------------------------------------------------------------------
// Fused decoupled-lookback scan + W->fp16 conversion.
// blockIdx.y <  NCHUNK : scan CTA for (xblock=blockIdx.x, chunk=blockIdx.y)
// blockIdx.y >= NCHUNK : W conversion (512 CTAs, 8 float4 per thread)
// Total 1024 CTAs -> all co-resident in one wave; lookback is short.
// ---------------------------------------------------------------------------
#define WROWS 64
__global__ void scan_fused_kernel(const float* __restrict__ x,
                                  const float* __restrict__ fparam,
                                  const float* __restrict__ xml,
                                  const float* __restrict__ W) {
    if (blockIdx.y >= NCHUNK) {
        // ---- W conversion: 512 blocks * 256 thr * 8 float4 = DIM*DIM ----
        int idx = (blockIdx.y - NCHUNK) * gridDim.x + blockIdx.x;
        int q = idx * blockDim.x + threadIdx.x;
        const int QE = (DIM * DIM / 4) / 8;   // 131072
#pragma unroll
        for (int r = 0; r < 8; r++) {
            float4 v = ((const float4*)W)[q + r * QE];
            ((__half2*)g_wh)[(q + r * QE) * 2]     = __floats2half2_rn(v.x, v.y);
            ((__half2*)g_wh)[(q + r * QE) * 2 + 1] = __floats2half2_rn(v.z, v.w);
        }
        return;
    }

    int xb = blockIdx.x, c = blockIdx.y, tid = threadIdx.x;
    int d = xb * 256 + tid;
    float f = sigmoidf_(fparam[d]);
    float omf = 1.0f - f;
    float fC = f;
#pragma unroll
    for (int i = 0; i < 7; i++) fC *= fC;     // f^128 = f^CHUNK

    const float* xp = x + (size_t)c * CHUNK * DIM + d;

    // ---- phase 1: chunk-local scan (zero seed) ----
    float y = 0.0f;
#pragma unroll 16
    for (int i = 0; i < CHUNK; i++)
        y = fmaf(f, y, omf * xp[(size_t)i * DIM]);

    // ---- publish aggregate Y[c] ----
    g_carry[c * DIM + d] = y;
    __threadfence();
    __syncthreads();
    if (tid == 0) st_rel(&g_flag[c * XBLKS + xb], 1);

    // ---- lookback: mprev = M[c-1] ----
    float mprev;
    if (c == 0) {
        mprev = xml[d];
    } else {
        __shared__ int s_stop;
        if (tid < 32) {
            // warp-parallel poll: lane k covers cc = c-1-k and c-33-k
            int cc1 = c - 1 - tid;
            int cc2 = cc1 - 32;
            while (true) {
                int fl1 = (cc1 >= 0) ? ld_acq(&g_flag[cc1 * XBLKS + xb]) : 3;
                int fl2 = (cc2 >= 0) ? ld_acq(&g_flag[cc2 * XBLKS + xb]) : 3;
                bool ready = __all_sync(0xFFFFFFFFu, (fl1 != 0) && (fl2 != 0));
                if (ready) {
                    unsigned m1 = __ballot_sync(0xFFFFFFFFu, fl1 == 2);
                    unsigned m2 = __ballot_sync(0xFFFFFFFFu, fl2 == 2);
                    int stop;
                    if (m1)      stop = c - 1 - (__ffs(m1) - 1);
                    else if (m2) stop = c - 33 - (__ffs(m2) - 1);
                    else         stop = -1;
                    if (tid == 0) s_stop = stop;
                    break;
                }
                __nanosleep(64);
            }
        }
        __syncthreads();
        int stop = s_stop;
        // acc = sum_{cc=stop+1..c-1} fC^(c-1-cc) * Y[cc]  (+ prefix/xml tail)
        float acc = 0.0f, factor = 1.0f;
        for (int cc = c - 1; cc > stop; cc--) {
            acc = fmaf(factor, g_carry[cc * DIM + d], acc);
            factor *= fC;
        }
        if (stop >= 0) acc = fmaf(factor, g_prefix[stop * DIM + d], acc);
        else           acc = fmaf(factor, xml[d], acc);
        mprev = acc;
    }

    // ---- publish inclusive prefix M[c] = fC*M[c-1] + Y[c] ----
    g_prefix[c * DIM + d] = fmaf(fC, mprev, y);
    __threadfence();
    __syncthreads();
    if (tid == 0) st_rel(&g_flag[c * XBLKS + xb], 2);

    // ---- phase 3: seeded rescan (x chunk is L2-warm), write fp16 ----
    __half* yp = g_xmh + (size_t)c * CHUNK * DIM + d;
    float yy = mprev;
#pragma unroll 16
    for (int i = 0; i < CHUNK; i++) {
        yy = fmaf(f, yy, omf * xp[(size_t)i * DIM]);
        yp[(size_t)i * DIM] = __float2half_rn(yy);
    }
}

// ---------------------------------------------------------------------------
// fp16 mma.sync GEMM:  out[m,n] = sum_k A[m,k] * W[n,k]  (fp32 accum)
// Block tile 128x128x64, 128 threads = 4 warps (2m x 2n), warp tile 64x64.
// 2 CTAs/SM, 3-stage cp.async ring, boundary prime in ks=3 MMA shadow.
// Also re-zeroes g_flag for the next graph replay (stream-ordered after the
// scan kernel, so no reader exists until the next launch).
// (R13/R15-measured: 144.3-144.7us, tensor=78.5% — compute path unchanged)
// ---------------------------------------------------------------------------
#define BM 128
#define BN 128
#define BK 64
#define KTILES (DIM / BK)
#define A_BYTES (BM * 128)
#define B_BYTES (BN * 128)
#define STAGE_BYTES (A_BYTES + B_BYTES)
#define NSTAGE 3
#define SM_BYTES (NSTAGE * STAGE_BYTES)

#define MMA_F16(c, a, b0, b1)                                                 \
    asm volatile(                                                             \
        "mma.sync.aligned.m16n8k16.row.col.f32.f16.f16.f32 "                  \
        "{%0,%1,%2,%3},{%4,%5,%6,%7},{%8,%9},{%0,%1,%2,%3};\n"                \
        : "+f"((c)[0]), "+f"((c)[1]), "+f"((c)[2]), "+f"((c)[3])              \
        : "r"((a)[0]), "r"((a)[1]), "r"((a)[2]), "r"((a)[3]),                 \
          "r"(b0), "r"(b1))

__device__ __forceinline__ uint32_t smem_u32(const void* p) {
    uint32_t a;
    asm("{ .reg .u64 t; cvta.to.shared.u64 t, %1; cvt.u32.u64 %0, t; }" : "=r"(a) : "l"(p));
    return a;
}
__device__ __forceinline__ void cp16(uint32_t dst, const void* src) {
    asm volatile("cp.async.cg.shared.global [%0], [%1], 16;" :: "r"(dst), "l"(src));
}
__device__ __forceinline__ void cp_commit() {
    asm volatile("cp.async.commit_group;");
}
template <int N>
__device__ __forceinline__ void cp_wait() {
    asm volatile("cp.async.wait_group %0;" :: "n"(N));
}
__device__ __forceinline__ void ldsm4(unsigned* r, uint32_t addr) {
    asm volatile("ldmatrix.sync.aligned.m8n8.x4.shared.b16 {%0,%1,%2,%3}, [%4];"
                 : "=r"(r[0]), "=r"(r[1]), "=r"(r[2]), "=r"(r[3]) : "r"(addr));
}

__global__ __launch_bounds__(128, 2) void gemm_kernel(float* __restrict__ out) {
    extern __shared__ char smc[];
    uint32_t sb = smem_u32(smc);

    int tid = threadIdx.x;
    // flag reset for the next replay (scan already fully consumed them)
    int bid = blockIdx.y * gridDim.x + blockIdx.x;
    if (tid == 0 && bid < NCHUNK * XBLKS) g_flag[bid] = 0;

    int bm = blockIdx.y * BM, bn = blockIdx.x * BN;
    int warp = tid >> 5, lane = tid & 31;
    int wm = (warp & 1) * 64, wn = (warp >> 1) * 64;
    int grp = lane >> 2, tig = lane & 3;

    int lrow = tid >> 3;
    int lch = tid & 7;
    uint32_t stoffA = lrow * 128 + ((lch ^ (lrow & 7)) << 4);
    uint32_t stoffB = A_BYTES + stoffA;

    const __half* Ag = g_xmh + (size_t)(bm + lrow) * DIM + lch * 8;
    const __half* Bg = g_wh + (size_t)(bn + lrow) * DIM + lch * 8;

    uint32_t aBase[4]; int aR7[4];
    int aCC = lane >> 4;
    {
        int r = (lane & 7) + ((lane >> 3) & 1) * 8;
#pragma unroll
        for (int mt = 0; mt < 4; mt++) {
            int row = wm + mt * 16 + r;
            aBase[mt] = row * 128;
            aR7[mt] = row & 7;
        }
    }
    uint32_t bBase[4]; int bR7[4];
    int bCC = (lane >> 3) & 1;
    {
        int r = (lane & 7) + ((lane >> 4) & 1) * 8;
#pragma unroll
        for (int p = 0; p < 4; p++) {
            int row = wn + p * 16 + r;
            bBase[p] = A_BYTES + row * 128;
            bR7[p] = row & 7;
        }
    }

    float acc[4][8][4] = {};

    auto issue = [&](int t) {
        int slot = t % NSTAGE;
        uint32_t base = sb + slot * STAGE_BYTES;
        const __half* Ak = Ag + t * BK;
        const __half* Bk = Bg + t * BK;
#pragma unroll
        for (int o = 0; o < 8; o++)
            cp16(base + stoffA + o * (16 * 128), Ak + (size_t)(o * 16) * DIM);
#pragma unroll
        for (int o = 0; o < 8; o++)
            cp16(base + stoffB + o * (16 * 128), Bk + (size_t)(o * 16) * DIM);
        cp_commit();
    };

    unsigned a[2][4][4], b[2][4][4];

    auto prime = [&](int q, uint32_t st, int kc) {
#pragma unroll
        for (int mt = 0; mt < 4; mt++)
            ldsm4(a[q][mt], st + aBase[mt] + (((kc + aCC) ^ aR7[mt]) << 4));
#pragma unroll
        for (int p = 0; p < 4; p++)
            ldsm4(b[q][p], st + bBase[p] + (((kc + bCC) ^ bR7[p]) << 4));
    };

    issue(0);
    issue(1);
    cp_wait<1>();
    __syncthreads();
    prime(0, sb, 0);

    int slot = 0;
    for (int j = 0; j < KTILES; j++) {
        uint32_t st = sb + slot * STAGE_BYTES;
        if (j + 2 < KTILES) issue(j + 2);

#pragma unroll
        for (int ks = 0; ks < 4; ks++) {
            int cur = ks & 1, nxt = cur ^ 1;
            if (ks < 3) {
                prime(nxt, st, 2 * (ks + 1));
            } else if (j + 1 < KTILES) {
                if (j + 2 < KTILES) { cp_wait<1>(); }
                else { cp_wait<0>(); }
                __syncthreads();
                int slot2 = slot + 1 == NSTAGE ? 0 : slot + 1;
                prime(nxt, sb + slot2 * STAGE_BYTES, 0);
            }
#pragma unroll
            for (int mt = 0; mt < 4; mt++)
#pragma unroll
                for (int p = 0; p < 4; p++) {
                    MMA_F16(acc[mt][2 * p], a[cur][mt], b[cur][p][0], b[cur][p][1]);
                    MMA_F16(acc[mt][2 * p + 1], a[cur][mt], b[cur][p][2], b[cur][p][3]);
                }
        }

        slot++; if (slot == NSTAGE) slot = 0;
    }

#pragma unroll
    for (int mt = 0; mt < 4; mt++) {
#pragma unroll
        for (int nt = 0; nt < 8; nt++) {
            int row = bm + wm + mt * 16 + grp;
            int col = bn + wn + nt * 8 + tig * 2;
            float2 v0 = make_float2(acc[mt][nt][0], acc[mt][nt][1]);
            float2 v1 = make_float2(acc[mt][nt][2], acc[mt][nt][3]);
            *(float2*)(out + (size_t)row * DIM + col) = v0;
            *(float2*)(out + (size_t)(row + 8) * DIM + col) = v1;
        }
    }
}

// ---------------------------------------------------------------------------
extern "C" void kernel_launch(void* const* d_in, const int* in_sizes, int n_in,
                              void* d_out, int out_size) {
    const float* x      = (const float*)d_in[0];
    const float* xml    = (const float*)d_in[1];
    const float* fparam = (const float*)d_in[2];
    const float* W      = (const float*)d_in[3];
    float* out = (float*)d_out;

    scan_fused_kernel<<<dim3(XBLKS, NCHUNK + WROWS), 256>>>(x, fparam, xml, W);

    static bool attr_set = false;
    if (!attr_set) {
        cudaFuncSetAttribute(gemm_kernel, cudaFuncAttributeMaxDynamicSharedMemorySize, SM_BYTES);
        attr_set = true;
    }
    gemm_kernel<<<dim3(DIM / BN, LSEQ / BM), 128, SM_BYTES>>>(out);
}